// round 14
// baseline (speedup 1.0000x reference)
#include <cuda_runtime.h>
#include <math_constants.h>

#define BATCH 256
#define SEGMAX 8200
#define RROWS 4
#define TPB 256
#define WPB (TPB / 32)

__device__ int g_seg[3][SEGMAX];
__device__ int g_pbase[3];
__device__ int g_cend[3];
__device__ int g_cstart[3];
__device__ unsigned g_barcnt = 0;
__device__ unsigned g_bargen = 0;

// Sense-reversing grid barrier. ALL threads of ALL (co-resident) blocks must call.
__device__ __forceinline__ void grid_barrier() {
    __threadfence();
    __syncthreads();
    if (threadIdx.x == 0) {
        unsigned gen = atomicAdd(&g_bargen, 0u);
        if (atomicAdd(&g_barcnt, 1u) == (unsigned)gridDim.x - 1u) {
            atomicExch(&g_barcnt, 0u);
            __threadfence();
            atomicAdd(&g_bargen, 1u);   // release
        } else {
            while (atomicAdd(&g_bargen, 0u) == gen) { }   // acquire spin
        }
    }
    __syncthreads();
}

// Grouped reduction over 4 row-accumulators + 4 parallel parent updates
// (scalar fallback paths).
__device__ __forceinline__ void reduce_and_update(
    float acc[RROWS], int lane, int pnode,
    const float* srcBase, float* dstBase, int num_nodes) {
#pragma unroll
    for (int r = 0; r < RROWS; r++) {
        acc[r] += __shfl_xor_sync(0xffffffffu, acc[r], 16);
        acc[r] += __shfl_xor_sync(0xffffffffu, acc[r], 8);
    }
    int g = lane >> 3;
    float w = acc[0];
    w = (g == 1) ? acc[1] : w;
    w = (g == 2) ? acc[2] : w;
    w = (g == 3) ? acc[3] : w;
    w += __shfl_xor_sync(0xffffffffu, w, 4);
    w += __shfl_xor_sync(0xffffffffu, w, 2);
    w += __shfl_xor_sync(0xffffffffu, w, 1);
    if ((lane & 7) == 0) {
        float lse = __logf(w);
        const float* rowIn  = srcBase + (size_t)g * num_nodes;
        float*       rowOut = dstBase + (size_t)g * num_nodes;
        rowOut[pnode] = fmaxf(rowIn[pnode], lse);
    }
}

// Complete one fast-path segment: stores, masked exp, half-warp butterfly,
// parent updates. All offsets are 32-bit flat indices.
__device__ __forceinline__ void complete_item(
    const float* __restrict__ in, float* __restrict__ out,
    float4 vA, float4 vB, unsigned sA, unsigned sB,
    int shA, int shB, int n, unsigned pA, unsigned pB,
    int q, int lane) {
    const float NEG_INF = -CUDART_INF_F;
    *(float4*)(out + sA) = vA;
    *(float4*)(out + sB) = vB;
    float accA = 0.0f, accB = 0.0f;
    {
        float xs[4] = {vA.x, vA.y, vA.z, vA.w};
#pragma unroll
        for (int c = 0; c < 4; c++) {
            bool ok = (unsigned)(q + c - shA) < (unsigned)n;
            accA += __expf(ok ? xs[c] : NEG_INF);
        }
    }
    {
        float xs[4] = {vB.x, vB.y, vB.z, vB.w};
#pragma unroll
        for (int c = 0; c < 4; c++) {
            bool ok = (unsigned)(q + c - shB) < (unsigned)n;
            accB += __expf(ok ? xs[c] : NEG_INF);
        }
    }
#pragma unroll
    for (int o = 1; o <= 8; o <<= 1) {
        accA += __shfl_xor_sync(0xffffffffu, accA, o);
        accB += __shfl_xor_sync(0xffffffffu, accB, o);
    }
    if ((lane & 15) == 0) {
        out[pA] = fmaxf(in[pA], __logf(accA));
        out[pB] = fmaxf(in[pB], __logf(accB));
    }
}

// Upper-level segment LSE (children read from out via __ldcg, cross-SM safe).
template <int SLOTS>
__device__ __forceinline__ void upper_seg(
    const float* __restrict__ in, float* __restrict__ out,
    int lvl, int i, int rg, int lane, int num_nodes) {
    const int* seg = g_seg[lvl];
    int cbase = seg[i];
    int n = seg[i + 1] - cbase;
    int pnode = g_pbase[lvl] + i;
    int cend = g_cend[lvl];

    size_t rowoff = (size_t)(rg * RROWS) * num_nodes;
    const float* srcBase = in + rowoff;
    float*       dstBase = out + rowoff;
    const float NEG_INF = -CUDART_INF_F;
    float acc[RROWS];

    if (n <= SLOTS * 32 && cbase + SLOTS * 32 <= cend) {
        float v[RROWS][SLOTS];
#pragma unroll
        for (int r = 0; r < RROWS; r++) {
            const float* src = dstBase + (size_t)r * num_nodes + cbase;
#pragma unroll
            for (int t = 0; t < SLOTS; t++) v[r][t] = __ldcg(src + lane + t * 32);
        }
#pragma unroll
        for (int r = 0; r < RROWS; r++) {
            acc[r] = 0.0f;
#pragma unroll
            for (int t = 0; t < SLOTS; t++) {
                float x = (lane + t * 32 < n) ? v[r][t] : NEG_INF;
                acc[r] += __expf(x);
            }
        }
    } else {
#pragma unroll
        for (int r = 0; r < RROWS; r++) acc[r] = 0.0f;
        for (int k = lane; k < n; k += 32)
#pragma unroll
            for (int r = 0; r < RROWS; r++)
                acc[r] += __expf(__ldcg(dstBase + (size_t)r * num_nodes + cbase + k));
    }
    reduce_and_update(acc, lane, pnode, srcBase, dstBase, num_nodes);
}

__global__ void __launch_bounds__(TPB)
fused_kernel(const float* __restrict__ in, float* __restrict__ out,
             const int* __restrict__ f0, const int* __restrict__ M0,
             const int* __restrict__ c0, const int* __restrict__ p0, int N0, int P0,
             const int* __restrict__ f1, const int* __restrict__ M1,
             const int* __restrict__ c1, const int* __restrict__ p1, int N1, int P1,
             const int* __restrict__ f2, const int* __restrict__ M2,
             const int* __restrict__ c2, const int* __restrict__ p2, int N2, int P2,
             int num_nodes) {
    int lane = threadIdx.x & 31;
    int gw = blockIdx.x * WPB + (threadIdx.x >> 5);
    int nw = gridDim.x * WPB;
    int tid = blockIdx.x * TPB + threadIdx.x;
    int nthreads = gridDim.x * TPB;

    // ---- Phase P: segment decode for all three levels ----
    {
        int Mv = M2[0];
        for (int k = tid; k < N2; k += nthreads) {
            int i = f2[k] / Mv;
            if (k == 0 || (f2[k - 1] / Mv) != i) g_seg[2][i] = c2[0] + k;
        }
        Mv = M1[0];
        for (int k = tid; k < N1; k += nthreads) {
            int i = f1[k] / Mv;
            if (k == 0 || (f1[k - 1] / Mv) != i) g_seg[1][i] = c1[0] + k;
        }
        Mv = M0[0];
        for (int k = tid; k < N0; k += nthreads) {
            int i = f0[k] / Mv;
            if (k == 0 || (f0[k - 1] / Mv) != i) g_seg[0][i] = c0[0] + k;
        }
        if (tid == 0) {
            g_seg[2][P2] = c2[0] + N2; g_pbase[2] = p2[0]; g_cend[2] = c2[0] + N2; g_cstart[2] = c2[0];
            g_seg[1][P1] = c1[0] + N1; g_pbase[1] = p1[0]; g_cend[1] = c1[0] + N1; g_cstart[1] = c1[0];
            g_seg[0][P0] = c0[0] + N0; g_pbase[0] = p0[0]; g_cend[0] = c0[0] + N0; g_cstart[0] = c0[0];
        }
    }
    grid_barrier();

    // ---- Phase 2 (leaves): fused copy in->out + LSE into level-2 parents ----
    {
        const int* seg = g_seg[2];
        int pbase = g_pbase[2];
        int leafStart = g_cstart[2];
        int leafEnd = g_cend[2];
        const float NEG_INF = -CUDART_INF_F;
        unsigned nn = (unsigned)num_nodes;
        int half = lane >> 4;
        int q = (lane & 15) << 2;

        // --- Sweep A: pair fast path. Each iteration handles segments 2j and
        // 2j+1 for one rowgroup: shared row bases, 4 LDG.128 in flight (MLP=4),
        // adjacent windows overlap -> in-warp L1 reuse.
        int npairs = (P2 + 1) >> 1;
        int totalA = npairs << 6;
        for (int item = gw; item < totalA; item += nw) {
            int j = item >> 6;
            int rg = item & 63;
            int s0 = j << 1;
            int s1 = s0 + 1;
            int cb0 = seg[s0];
            int cb1 = seg[s1];               // == end of s0
            int e1  = seg[s1 + 1];           // sentinel-safe for s1 == P2-1
            int n0 = cb1 - cb0;
            int n1 = e1 - cb1;
            bool ok0 = (n0 <= 61) && (cb0 >= leafStart + 4) && (cb0 + 64 <= leafEnd);
            bool ok1 = (s1 < P2) && (n1 <= 61) && (cb1 >= leafStart + 4) && (cb1 + 64 <= leafEnd);

            unsigned rowA = (unsigned)(rg * RROWS + half) * nn;
            unsigned rowB = rowA + 2u * nn;

            float4 vA0, vB0, vA1, vB1;
            unsigned eA0 = 0, eB0 = 0, eA1 = 0, eB1 = 0;
            int shA0 = 0, shB0 = 0, shA1 = 0, shB1 = 0;
            if (ok0) {
                unsigned fA = rowA + (unsigned)cb0;
                unsigned fB = rowB + (unsigned)cb0;
                shA0 = (int)(fA & 3u); shB0 = (int)(fB & 3u);
                eA0 = fA - shA0 + q;   eB0 = fB - shB0 + q;
                vA0 = *(const float4*)(in + eA0);
                vB0 = *(const float4*)(in + eB0);
            }
            if (ok1) {
                unsigned fA = rowA + (unsigned)cb1;
                unsigned fB = rowB + (unsigned)cb1;
                shA1 = (int)(fA & 3u); shB1 = (int)(fB & 3u);
                eA1 = fA - shA1 + q;   eB1 = fB - shB1 + q;
                vA1 = *(const float4*)(in + eA1);
                vB1 = *(const float4*)(in + eB1);
            }
            if (ok0)
                complete_item(in, out, vA0, vB0, eA0, eB0, shA0, shB0, n0,
                              rowA + (unsigned)(pbase + s0),
                              rowB + (unsigned)(pbase + s0), q, lane);
            if (ok1)
                complete_item(in, out, vA1, vB1, eA1, eB1, shA1, shB1, n1,
                              rowA + (unsigned)(pbase + s1),
                              rowB + (unsigned)(pbase + s1), q, lane);
        }

        // --- Sweep B: edge segments (scalar predicated path) ---
        int total = P2 << 6;
        for (int item = gw; item < total; item += nw) {
            int i = item >> 6;
            int rg = item & 63;
            int cbase = seg[i];
            int n = seg[i + 1] - cbase;
            if (n <= 61 && cbase >= leafStart + 4 && cbase + 64 <= leafEnd)
                continue;   // handled by sweep A
            int pnode = pbase + i;
            size_t rowoff = (size_t)(rg * RROWS) * num_nodes;
            const float* srcBase = in + rowoff;
            float*       dstBase = out + rowoff;
            float acc[RROWS];
            if (n <= 64) {
                float v[RROWS][2];
#pragma unroll
                for (int r = 0; r < RROWS; r++) {
                    const float* src = srcBase + (size_t)r * num_nodes;
                    v[r][0] = (lane < n)      ? src[cbase + lane]      : NEG_INF;
                    v[r][1] = (lane + 32 < n) ? src[cbase + lane + 32] : NEG_INF;
                }
#pragma unroll
                for (int r = 0; r < RROWS; r++) {
                    float* dst = dstBase + (size_t)r * num_nodes;
                    if (lane < n)      dst[cbase + lane]      = v[r][0];
                    if (lane + 32 < n) dst[cbase + lane + 32] = v[r][1];
                }
#pragma unroll
                for (int r = 0; r < RROWS; r++)
                    acc[r] = __expf(v[r][0]) + __expf(v[r][1]);
            } else {
#pragma unroll
                for (int r = 0; r < RROWS; r++) acc[r] = 0.0f;
                for (int k = lane; k < n; k += 32) {
#pragma unroll
                    for (int r = 0; r < RROWS; r++) {
                        float x = srcBase[(size_t)r * num_nodes + cbase + k];
                        dstBase[(size_t)r * num_nodes + cbase + k] = x;
                        acc[r] += __expf(x);
                    }
                }
            }
            reduce_and_update(acc, lane, pnode, srcBase, dstBase, num_nodes);
        }
    }
    grid_barrier();

    // ---- Phase 1: level-1 parents (children = level-2 nodes, L2-hot) ----
    {
        int total = P1 << 6;
        for (int item = gw; item < total; item += nw)
            upper_seg<2>(in, out, 1, item >> 6, item & 63, lane, num_nodes);
    }
    grid_barrier();

    // ---- Phase 0: root ----
    {
        int total = P0 << 6;
        for (int item = gw; item < total; item += nw)
            upper_seg<4>(in, out, 0, item >> 6, item & 63, lane, num_nodes);
    }
}

extern "C" void kernel_launch(void* const* d_in, const int* in_sizes, int n_in,
                              void* d_out, int out_size) {
    // metadata order: scores, p0,f0,c0,P0,M0, p1,f1,c1,P1,M1, p2,f2,c2,P2,M2
    const float* scores = (const float*)d_in[0];
    const int* p0 = (const int*)d_in[1];
    const int* f0 = (const int*)d_in[2];
    const int* c0 = (const int*)d_in[3];
    const int* M0 = (const int*)d_in[5];
    const int* p1 = (const int*)d_in[6];
    const int* f1 = (const int*)d_in[7];
    const int* c1 = (const int*)d_in[8];
    const int* M1 = (const int*)d_in[10];
    const int* p2 = (const int*)d_in[11];
    const int* f2 = (const int*)d_in[12];
    const int* c2 = (const int*)d_in[13];
    const int* M2 = (const int*)d_in[15];

    int P0 = in_sizes[1],  N0 = in_sizes[2];
    int P1 = in_sizes[6],  N1 = in_sizes[7];
    int P2 = in_sizes[11], N2 = in_sizes[12];
    int num_nodes = in_sizes[0] / BATCH;
    float* out = (float*)d_out;

    // Size the persistent grid to guaranteed-co-resident blocks.
    int sms = 148, occ = 1;
    cudaDeviceGetAttribute(&sms, cudaDevAttrMultiProcessorCount, 0);
    cudaOccupancyMaxActiveBlocksPerMultiprocessor(&occ, fused_kernel, TPB, 0);
    if (occ < 1) occ = 1;
    if (occ > 8) occ = 8;
    int grid = sms * occ;

    fused_kernel<<<grid, TPB>>>(scores, out,
                                f0, M0, c0, p0, N0, P0,
                                f1, M1, c1, p1, N1, P1,
                                f2, M2, c2, p2, N2, P2,
                                num_nodes);
}

// round 15
// speedup vs baseline: 1.0664x; 1.0664x over previous
#include <cuda_runtime.h>
#include <math_constants.h>

#define BATCH 256
#define SEGMAX 8200
#define RROWS 4
#define TPB 256
#define WPB (TPB / 32)

__device__ int g_seg[3][SEGMAX];
__device__ int g_pbase[3];
__device__ int g_cend[3];
__device__ int g_cstart[3];
__device__ unsigned g_barcnt = 0;
__device__ unsigned g_bargen = 0;

// Sense-reversing grid barrier. ALL threads of ALL (co-resident) blocks must call.
__device__ __forceinline__ void grid_barrier() {
    __threadfence();
    __syncthreads();
    if (threadIdx.x == 0) {
        unsigned gen = atomicAdd(&g_bargen, 0u);
        if (atomicAdd(&g_barcnt, 1u) == (unsigned)gridDim.x - 1u) {
            atomicExch(&g_barcnt, 0u);
            __threadfence();
            atomicAdd(&g_bargen, 1u);   // release
        } else {
            while (atomicAdd(&g_bargen, 0u) == gen) { }   // acquire spin
        }
    }
    __syncthreads();
}

// Grouped reduction over 4 row-accumulators + 4 parallel parent updates
// (scalar fallback paths).
__device__ __forceinline__ void reduce_and_update(
    float acc[RROWS], int lane, int pnode,
    const float* srcBase, float* dstBase, int num_nodes) {
#pragma unroll
    for (int r = 0; r < RROWS; r++) {
        acc[r] += __shfl_xor_sync(0xffffffffu, acc[r], 16);
        acc[r] += __shfl_xor_sync(0xffffffffu, acc[r], 8);
    }
    int g = lane >> 3;
    float w = acc[0];
    w = (g == 1) ? acc[1] : w;
    w = (g == 2) ? acc[2] : w;
    w = (g == 3) ? acc[3] : w;
    w += __shfl_xor_sync(0xffffffffu, w, 4);
    w += __shfl_xor_sync(0xffffffffu, w, 2);
    w += __shfl_xor_sync(0xffffffffu, w, 1);
    if ((lane & 7) == 0) {
        float lse = __logf(w);
        const float* rowIn  = srcBase + (size_t)g * num_nodes;
        float*       rowOut = dstBase + (size_t)g * num_nodes;
        rowOut[pnode] = fmaxf(rowIn[pnode], lse);
    }
}

// Upper-level segment LSE (children read from out via __ldcg, cross-SM safe).
template <int SLOTS>
__device__ __forceinline__ void upper_seg(
    const float* __restrict__ in, float* __restrict__ out,
    int lvl, int i, int rg, int lane, int num_nodes) {
    const int* seg = g_seg[lvl];
    int cbase = seg[i];
    int n = seg[i + 1] - cbase;
    int pnode = g_pbase[lvl] + i;
    int cend = g_cend[lvl];

    size_t rowoff = (size_t)(rg * RROWS) * num_nodes;
    const float* srcBase = in + rowoff;
    float*       dstBase = out + rowoff;
    const float NEG_INF = -CUDART_INF_F;
    float acc[RROWS];

    if (n <= SLOTS * 32 && cbase + SLOTS * 32 <= cend) {
        float v[RROWS][SLOTS];
#pragma unroll
        for (int r = 0; r < RROWS; r++) {
            const float* src = dstBase + (size_t)r * num_nodes + cbase;
#pragma unroll
            for (int t = 0; t < SLOTS; t++) v[r][t] = __ldcg(src + lane + t * 32);
        }
#pragma unroll
        for (int r = 0; r < RROWS; r++) {
            acc[r] = 0.0f;
#pragma unroll
            for (int t = 0; t < SLOTS; t++) {
                float x = (lane + t * 32 < n) ? v[r][t] : NEG_INF;
                acc[r] += __expf(x);
            }
        }
    } else {
#pragma unroll
        for (int r = 0; r < RROWS; r++) acc[r] = 0.0f;
        for (int k = lane; k < n; k += 32)
#pragma unroll
            for (int r = 0; r < RROWS; r++)
                acc[r] += __expf(__ldcg(dstBase + (size_t)r * num_nodes + cbase + k));
    }
    reduce_and_update(acc, lane, pnode, srcBase, dstBase, num_nodes);
}

__global__ void __launch_bounds__(TPB, 8)
fused_kernel(const float* __restrict__ in, float* __restrict__ out,
             const int* __restrict__ f0, const int* __restrict__ M0,
             const int* __restrict__ c0, const int* __restrict__ p0, int N0, int P0,
             const int* __restrict__ f1, const int* __restrict__ M1,
             const int* __restrict__ c1, const int* __restrict__ p1, int N1, int P1,
             const int* __restrict__ f2, const int* __restrict__ M2,
             const int* __restrict__ c2, const int* __restrict__ p2, int N2, int P2,
             int num_nodes) {
    int lane = threadIdx.x & 31;
    int gw = blockIdx.x * WPB + (threadIdx.x >> 5);
    int nw = gridDim.x * WPB;
    int tid = blockIdx.x * TPB + threadIdx.x;
    int nthreads = gridDim.x * TPB;

    // ---- Phase P: segment decode for all three levels ----
    {
        int Mv = M2[0];
        for (int k = tid; k < N2; k += nthreads) {
            int i = f2[k] / Mv;
            if (k == 0 || (f2[k - 1] / Mv) != i) g_seg[2][i] = c2[0] + k;
        }
        Mv = M1[0];
        for (int k = tid; k < N1; k += nthreads) {
            int i = f1[k] / Mv;
            if (k == 0 || (f1[k - 1] / Mv) != i) g_seg[1][i] = c1[0] + k;
        }
        Mv = M0[0];
        for (int k = tid; k < N0; k += nthreads) {
            int i = f0[k] / Mv;
            if (k == 0 || (f0[k - 1] / Mv) != i) g_seg[0][i] = c0[0] + k;
        }
        if (tid == 0) {
            g_seg[2][P2] = c2[0] + N2; g_pbase[2] = p2[0]; g_cend[2] = c2[0] + N2; g_cstart[2] = c2[0];
            g_seg[1][P1] = c1[0] + N1; g_pbase[1] = p1[0]; g_cend[1] = c1[0] + N1; g_cstart[1] = c1[0];
            g_seg[0][P0] = c0[0] + N0; g_pbase[0] = p0[0]; g_cend[0] = c0[0] + N0; g_cstart[0] = c0[0];
        }
    }
    grid_barrier();

    // ---- Phase 2 (leaves): fused copy in->out + LSE into level-2 parents ----
    // Exact R11 structure/mapping; 32-bit flat addressing in the fast path.
    {
        const int* seg = g_seg[2];
        int pbase = g_pbase[2];
        int leafStart = g_cstart[2];
        int leafEnd = g_cend[2];
        const float NEG_INF = -CUDART_INF_F;
        unsigned nn = (unsigned)num_nodes;
        int total = P2 << 6;   // i = item>>6, rg = item&63
        int half = lane >> 4;
        int q = (lane & 15) << 2;
        for (int item = gw; item < total; item += nw) {
            int i = item >> 6;
            int rg = item & 63;
            int cbase = seg[i];
            int n = seg[i + 1] - cbase;
            int pnode = pbase + i;

            if (n <= 61 && cbase >= leafStart + 4 && cbase + 64 <= leafEnd) {
                // === Vectorized fast path ===
                unsigned rowA = (unsigned)(rg * RROWS + half) * nn;
                unsigned rowB = rowA + 2u * nn;
                unsigned fA = rowA + (unsigned)cbase;
                unsigned fB = rowB + (unsigned)cbase;
                int shA = (int)(fA & 3u);
                int shB = (int)(fB & 3u);
                unsigned eA = fA - shA + q;
                unsigned eB = fB - shB + q;

                float4 vA = *(const float4*)(in + eA);
                float4 vB = *(const float4*)(in + eB);
                *(float4*)(out + eA) = vA;
                *(float4*)(out + eB) = vB;

                float accA = 0.0f, accB = 0.0f;
                {
                    float xs[4] = {vA.x, vA.y, vA.z, vA.w};
#pragma unroll
                    for (int c = 0; c < 4; c++) {
                        bool ok = (unsigned)(q + c - shA) < (unsigned)n;
                        accA += __expf(ok ? xs[c] : NEG_INF);
                    }
                }
                {
                    float xs[4] = {vB.x, vB.y, vB.z, vB.w};
#pragma unroll
                    for (int c = 0; c < 4; c++) {
                        bool ok = (unsigned)(q + c - shB) < (unsigned)n;
                        accB += __expf(ok ? xs[c] : NEG_INF);
                    }
                }
#pragma unroll
                for (int o = 1; o <= 8; o <<= 1) {
                    accA += __shfl_xor_sync(0xffffffffu, accA, o);
                    accB += __shfl_xor_sync(0xffffffffu, accB, o);
                }
                if ((lane & 15) == 0) {
                    unsigned pA = rowA + (unsigned)pnode;
                    unsigned pB = rowB + (unsigned)pnode;
                    out[pA] = fmaxf(in[pA], __logf(accA));
                    out[pB] = fmaxf(in[pB], __logf(accB));
                }
            } else {
                // === Scalar predicated path (edge segments / n>61) ===
                size_t rowoff = (size_t)(rg * RROWS) * num_nodes;
                const float* srcBase = in + rowoff;
                float*       dstBase = out + rowoff;
                float acc[RROWS];
                if (n <= 64) {
                    float v[RROWS][2];
#pragma unroll
                    for (int r = 0; r < RROWS; r++) {
                        const float* src = srcBase + (size_t)r * num_nodes;
                        v[r][0] = (lane < n)      ? src[cbase + lane]      : NEG_INF;
                        v[r][1] = (lane + 32 < n) ? src[cbase + lane + 32] : NEG_INF;
                    }
#pragma unroll
                    for (int r = 0; r < RROWS; r++) {
                        float* dst = dstBase + (size_t)r * num_nodes;
                        if (lane < n)      dst[cbase + lane]      = v[r][0];
                        if (lane + 32 < n) dst[cbase + lane + 32] = v[r][1];
                    }
#pragma unroll
                    for (int r = 0; r < RROWS; r++)
                        acc[r] = __expf(v[r][0]) + __expf(v[r][1]);
                } else {
#pragma unroll
                    for (int r = 0; r < RROWS; r++) acc[r] = 0.0f;
                    for (int k = lane; k < n; k += 32) {
#pragma unroll
                        for (int r = 0; r < RROWS; r++) {
                            float x = srcBase[(size_t)r * num_nodes + cbase + k];
                            dstBase[(size_t)r * num_nodes + cbase + k] = x;
                            acc[r] += __expf(x);
                        }
                    }
                }
                reduce_and_update(acc, lane, pnode, srcBase, dstBase, num_nodes);
            }
        }
    }
    grid_barrier();

    // ---- Phase 1: level-1 parents (children = level-2 nodes, L2-hot) ----
    {
        int total = P1 << 6;
        for (int item = gw; item < total; item += nw)
            upper_seg<2>(in, out, 1, item >> 6, item & 63, lane, num_nodes);
    }
    grid_barrier();

    // ---- Phase 0: root ----
    {
        int total = P0 << 6;
        for (int item = gw; item < total; item += nw)
            upper_seg<4>(in, out, 0, item >> 6, item & 63, lane, num_nodes);
    }
}

extern "C" void kernel_launch(void* const* d_in, const int* in_sizes, int n_in,
                              void* d_out, int out_size) {
    // metadata order: scores, p0,f0,c0,P0,M0, p1,f1,c1,P1,M1, p2,f2,c2,P2,M2
    const float* scores = (const float*)d_in[0];
    const int* p0 = (const int*)d_in[1];
    const int* f0 = (const int*)d_in[2];
    const int* c0 = (const int*)d_in[3];
    const int* M0 = (const int*)d_in[5];
    const int* p1 = (const int*)d_in[6];
    const int* f1 = (const int*)d_in[7];
    const int* c1 = (const int*)d_in[8];
    const int* M1 = (const int*)d_in[10];
    const int* p2 = (const int*)d_in[11];
    const int* f2 = (const int*)d_in[12];
    const int* c2 = (const int*)d_in[13];
    const int* M2 = (const int*)d_in[15];

    int P0 = in_sizes[1],  N0 = in_sizes[2];
    int P1 = in_sizes[6],  N1 = in_sizes[7];
    int P2 = in_sizes[11], N2 = in_sizes[12];
    int num_nodes = in_sizes[0] / BATCH;
    float* out = (float*)d_out;

    // Size the persistent grid to guaranteed-co-resident blocks.
    int sms = 148, occ = 1;
    cudaDeviceGetAttribute(&sms, cudaDevAttrMultiProcessorCount, 0);
    cudaOccupancyMaxActiveBlocksPerMultiprocessor(&occ, fused_kernel, TPB, 0);
    if (occ < 1) occ = 1;
    if (occ > 8) occ = 8;
    int grid = sms * occ;

    fused_kernel<<<grid, TPB>>>(scores, out,
                                f0, M0, c0, p0, N0, P0,
                                f1, M1, c1, p1, N1, P1,
                                f2, M2, c2, p2, N2, P2,
                                num_nodes);
}